// round 3
// baseline (speedup 1.0000x reference)
#include <cuda_runtime.h>
#include <math.h>

#define HWPX 16384        // 128*128
#define EPSF 1e-5f

__device__ __forceinline__ float siluf(float v) { return v / (1.0f + __expf(-v)); }

// One block per bg-group (128 blocks, 1024 threads, <=64 regs -> 32 warps/SM).
//   P1 : row/col means           (cold read, 2 warps per channel, ascending)
//   kA : 1x1 + 3-tap conv + silu (smem only)
//   P2 : sums of y, y^2          (L2-warm read, descending)
//   kB : softmax(gn_b) identity + norm scalars (smem only)
//   C  : wts + gate + output     (L2-warm read ascending; channels split across
//        two warp-groups, partial wts combined via smem; x read once, streamed out)
__global__ __launch_bounds__(1024, 1)
void mega(const float* __restrict__ x,
          const float* __restrict__ w1, const float* __restrict__ b1,
          const float* __restrict__ w3, const float* __restrict__ b3,
          const float* __restrict__ gnw, const float* __restrict__ gnb,
          float* __restrict__ out)
{
    extern __shared__ float sm[];
    float* s1  = sm;               // [16][256] silu(hw1); also col-sum scratch during P1
    float* s2  = sm + 4096;        // [16][256]
    float* hwb = sm + 8192;        // [16][258] means+halo; aliased as wts-partial in phase C

    __shared__ float w1s[256], w3s[768], b1s[16], b3s[16];
    __shared__ float statp[128], k1s[16], k2s[16], cpart[16], gbsh[16];
    __shared__ float Csm;

    const int bg   = blockIdx.x;
    const int tid  = threadIdx.x;
    const int lane = tid & 31;
    const int wid  = tid >> 5;                   // 0..31
    const float* xb = x   + (size_t)bg * 16 * HWPX;
    float*       ob = out + (size_t)bg * 16 * HWPX;

    // ---- stage tiny weights (overlaps cold read) ----
    if (tid < 256) w1s[tid] = __ldg(w1 + tid);
    if (tid < 768) w3s[tid] = __ldg(w3 + tid * 3 + 1);   // kw=1 column
    if (tid < 16) { b1s[tid] = __ldg(b1 + tid); b3s[tid] = __ldg(b3 + tid); gbsh[tid] = __ldg(gnb + tid); }

    // ================= P1: row + col means (2 warps/channel, ascending) =================
    {
        const int c = wid >> 1, sub = wid & 1;
        const float* g = xb + c * HWPX;
        float* hwc = hwb + c * 258;
        float4 cs = make_float4(0.f, 0.f, 0.f, 0.f);
        const int r0 = sub * 64;
        #pragma unroll 1
        for (int i0 = r0; i0 < r0 + 64; i0 += 8) {
            float4 v[8]; float r[8];
            #pragma unroll
            for (int k = 0; k < 8; k++) v[k] = __ldg((const float4*)(g + (i0 + k) * 128) + lane);
            #pragma unroll
            for (int k = 0; k < 8; k++) {
                cs.x += v[k].x; cs.y += v[k].y; cs.z += v[k].z; cs.w += v[k].w;
                r[k] = (v[k].x + v[k].y) + (v[k].z + v[k].w);
            }
            #pragma unroll
            for (int off = 16; off; off >>= 1) {
                #pragma unroll
                for (int k = 0; k < 8; k++) r[k] += __shfl_down_sync(0xffffffffu, r[k], off);
            }
            if (lane == 0) {
                #pragma unroll
                for (int k = 0; k < 8; k++) hwc[1 + i0 + k] = r[k] * (1.f / 128.f);
            }
        }
        ((float4*)s1)[(c * 2 + sub) * 32 + lane] = cs;   // col partial sums (scratch)
    }
    __syncthreads();
    // combine column means + conv halo
    for (int idx = tid; idx < 2048; idx += 1024) {
        const int c = idx >> 7, j = idx & 127;
        hwb[c * 258 + 129 + j] = (s1[(c * 2) * 128 + j] + s1[(c * 2 + 1) * 128 + j]) * (1.f / 128.f);
    }
    if (tid < 16) { hwb[tid * 258] = 0.f; hwb[tid * 258 + 257] = 0.f; }
    __syncthreads();

    // ================= kA: channel mix over concat length 256 =================
    for (int idx = tid; idx < 4096; idx += 1024) {
        const int o = idx >> 8, l = idx & 255;
        float a1 = b1s[o], a2 = b3s[o];
        #pragma unroll
        for (int i = 0; i < 16; i++) {
            const float* h = hwb + i * 258 + l;
            const float h0 = h[0], h1 = h[1], h2 = h[2];
            a1 = fmaf(w1s[o * 16 + i], h1, a1);
            const int wb = (o * 16 + i) * 3;
            a2 = fmaf(w3s[wb], h0, fmaf(w3s[wb + 1], h1, fmaf(w3s[wb + 2], h2, a2)));
        }
        s1[o * 256 + l] = siluf(a1);
        s2[o * 256 + l] = siluf(a2);
    }
    __syncthreads();

    // ================= P2: sums of y, y^2 (2 warps/channel, descending) =================
    {
        const int c = wid >> 1, sub = wid & 1;
        const float* g = xb + c * HWPX;
        const float4 wa = *(const float4*)(s1 + c * 256 + 128 + 4 * lane);
        const float4 wb = *(const float4*)(s2 + c * 256 + 128 + 4 * lane);
        float sa = 0.f, qa = 0.f, sb = 0.f, qb = 0.f;
        const int r0 = sub * 64;
        #pragma unroll 1
        for (int i0 = r0 + 56; i0 >= r0; i0 -= 8) {
            float4 v[8];
            #pragma unroll
            for (int k = 0; k < 8; k++) v[k] = __ldg((const float4*)(g + (i0 + k) * 128) + lane);
            #pragma unroll
            for (int k = 0; k < 8; k++) {
                const float h1 = s1[c * 256 + i0 + k];
                const float h2 = s2[c * 256 + i0 + k];
                float p;
                p = v[k].x * h1 * wa.x; sa += p; qa = fmaf(p, p, qa);
                p = v[k].y * h1 * wa.y; sa += p; qa = fmaf(p, p, qa);
                p = v[k].z * h1 * wa.z; sa += p; qa = fmaf(p, p, qa);
                p = v[k].w * h1 * wa.w; sa += p; qa = fmaf(p, p, qa);
                p = v[k].x * h2 * wb.x; sb += p; qb = fmaf(p, p, qb);
                p = v[k].y * h2 * wb.y; sb += p; qb = fmaf(p, p, qb);
                p = v[k].z * h2 * wb.z; sb += p; qb = fmaf(p, p, qb);
                p = v[k].w * h2 * wb.w; sb += p; qb = fmaf(p, p, qb);
            }
        }
        #pragma unroll
        for (int off = 16; off; off >>= 1) {
            sa += __shfl_down_sync(0xffffffffu, sa, off);
            qa += __shfl_down_sync(0xffffffffu, qa, off);
            sb += __shfl_down_sync(0xffffffffu, sb, off);
            qb += __shfl_down_sync(0xffffffffu, qb, off);
        }
        if (lane == 0) {
            statp[wid * 4 + 0] = sa; statp[wid * 4 + 1] = qa;
            statp[wid * 4 + 2] = sb; statp[wid * 4 + 3] = qb;
        }
    }
    __syncthreads();

    // ================= kB: scalars =================
    if (tid < 16) {
        float m = -1e30f;
        #pragma unroll
        for (int i = 0; i < 16; i++) m = fmaxf(m, gbsh[i]);
        float se = 0.f;
        #pragma unroll
        for (int i = 0; i < 16; i++) se += __expf(gbsh[i] - m);
        const float a = __expf(gbsh[tid] - m) / se;        // a1 == a2 == softmax(gn_b)
        const float S1 = statp[(tid * 2) * 4 + 0] + statp[(tid * 2 + 1) * 4 + 0];
        const float Q1 = statp[(tid * 2) * 4 + 1] + statp[(tid * 2 + 1) * 4 + 1];
        const float S2 = statp[(tid * 2) * 4 + 2] + statp[(tid * 2 + 1) * 4 + 2];
        const float Q2 = statp[(tid * 2) * 4 + 3] + statp[(tid * 2 + 1) * 4 + 3];
        const float mu1 = S1 * (1.f / 16384.f);
        const float r1  = rsqrtf(Q1 * (1.f / 16384.f) - mu1 * mu1 + EPSF);
        const float mu2 = S2 * (1.f / 16384.f);
        const float r2  = rsqrtf(Q2 * (1.f / 16384.f) - mu2 * mu2 + EPSF);
        const float gw = __ldg(gnw + tid);
        k1s[tid] = a * gw * r1;
        k2s[tid] = a * gw * r2;
        cpart[tid] = a * (2.f * gbsh[tid] - gw * (mu1 * r1 + mu2 * r2));
    }
    __syncthreads();
    if (tid == 0) {
        float s = 0.f;
        #pragma unroll
        for (int i = 0; i < 16; i++) s += cpart[i];
        Csm = s;
    }
    for (int idx = tid; idx < 2048; idx += 1024) {   // fold k into i-side tables
        const int c = idx >> 7, i = idx & 127;
        s1[c * 256 + i] *= k1s[c];
        s2[c * 256 + i] *= k2s[c];
    }
    __syncthreads();

    // ================= C: wts + gate + output (channel-split warp-groups) =================
    {
        float* wpart = hwb;                       // 2*16*128 floats = 16 KB, alias
        const int half  = wid >> 4;               // 0: c0-7, 1: c8-15
        const int rl    = wid & 15;               // row within 16-row slab
        const int cbase = half * 8;
        const float Cc = Csm;
        #pragma unroll 1
        for (int s = 0; s < 8; s++) {
            const int i = s * 16 + rl;
            float4 v[8];
            float4 acc = half ? make_float4(0.f, 0.f, 0.f, 0.f)
                              : make_float4(Cc, Cc, Cc, Cc);
            #pragma unroll
            for (int cc = 0; cc < 8; cc++) {
                const int c = cbase + cc;
                v[cc] = __ldcs((const float4*)(xb + c * HWPX + i * 128) + lane);
                const float a1 = s1[c * 256 + i];
                const float a2 = s2[c * 256 + i];
                const float4 j1 = *(const float4*)(s1 + c * 256 + 128 + 4 * lane);
                const float4 j2 = *(const float4*)(s2 + c * 256 + 128 + 4 * lane);
                acc.x += v[cc].x * fmaf(a1, j1.x, a2 * j2.x);
                acc.y += v[cc].y * fmaf(a1, j1.y, a2 * j2.y);
                acc.z += v[cc].z * fmaf(a1, j1.z, a2 * j2.z);
                acc.w += v[cc].w * fmaf(a1, j1.w, a2 * j2.w);
            }
            ((float4*)wpart)[(half * 16 + rl) * 32 + lane] = acc;
            __syncthreads();
            const float4 wA = ((float4*)wpart)[rl * 32 + lane];
            const float4 wB = ((float4*)wpart)[(16 + rl) * 32 + lane];
            float4 sw;
            sw.x = siluf(wA.x + wB.x);
            sw.y = siluf(wA.y + wB.y);
            sw.z = siluf(wA.z + wB.z);
            sw.w = siluf(wA.w + wB.w);
            #pragma unroll
            for (int cc = 0; cc < 8; cc++) {
                float4 o4;
                o4.x = v[cc].x * sw.x; o4.y = v[cc].y * sw.y;
                o4.z = v[cc].z * sw.z; o4.w = v[cc].w * sw.w;
                __stcs((float4*)(ob + (cbase + cc) * HWPX + i * 128) + lane, o4);
            }
            __syncthreads();   // wpart reused next slab
        }
    }
}

// ---------------- launch ----------------
extern "C" void kernel_launch(void* const* d_in, const int* in_sizes, int n_in,
                              void* d_out, int out_size) {
    const float* x    = (const float*)d_in[0];
    const float* w1   = (const float*)d_in[1];
    const float* b1   = (const float*)d_in[2];
    const float* w3   = (const float*)d_in[3];
    const float* b3   = (const float*)d_in[4];
    const float* gn_w = (const float*)d_in[5];
    const float* gn_b = (const float*)d_in[6];
    float* out = (float*)d_out;

    const int smem_bytes = (4096 + 4096 + 16 * 258) * (int)sizeof(float);  // 49280 B
    static bool attr_done = false;
    if (!attr_done) {
        cudaFuncSetAttribute(mega, cudaFuncAttributeMaxDynamicSharedMemorySize, smem_bytes);
        attr_done = true;
    }
    mega<<<128, 1024, smem_bytes>>>(x, w1, b1, w3, b3, gn_w, gn_b, out);
}

// round 4
// speedup vs baseline: 1.0006x; 1.0006x over previous
#include <cuda_runtime.h>
#include <math.h>

#define HWPX 16384        // 128*128
#define EPSF 1e-5f

// ---------------- global exchange scratch (static, no allocations) ----------------
__device__ float g_rowm[128][2][16 * 64];    // row means of own half-rows
__device__ float g_colp[128][2][16 * 128];   // column partial sums
__device__ float g_stat[128][2][64];         // P2 stat partials
__device__ int   g_flag1[128][2];            // zero-initialized; consumer resets -> stays 0 across launches
__device__ int   g_flag2[128][2];

__device__ __forceinline__ float siluf(float v) { return v / (1.0f + __expf(-v)); }

// 256 blocks (2 per bg-group, row-split halves), 256 threads, 2 CTAs/SM guaranteed.
// Phases P1 -> [exchange] -> kA -> P2 -> [exchange] -> kB -> C, with R2's inner loops.
__global__ __launch_bounds__(256, 2)
void mega(const float* __restrict__ x,
          const float* __restrict__ w1, const float* __restrict__ b1,
          const float* __restrict__ w3, const float* __restrict__ b3,
          const float* __restrict__ gnw, const float* __restrict__ gnb,
          float* __restrict__ out)
{
    extern __shared__ float sm[];
    float* s1  = sm;               // [16][256] silu tables; first 2048 floats double as col-partial scratch in P1
    float* s2  = sm + 4096;        // [16][256]
    float* hwb = sm + 8192;        // [16][258] means + conv halo

    __shared__ float w1s[256], w3s[768], b1s[16], b3s[16], gbsh[16];
    __shared__ float statp[64], k1s[16], k2s[16], cpart[16];
    __shared__ float Csm;

    const int bg  = blockIdx.x >> 1;
    const int hf  = blockIdx.x & 1;          // which row half this block owns
    const int ph  = hf ^ 1;
    const int r0  = hf * 64;
    const int pr0 = ph * 64;
    const int tid = threadIdx.x;
    const int lane = tid & 31;
    const int wid  = tid >> 5;               // 0..7
    const float* xb = x   + (size_t)bg * 16 * HWPX;
    float*       ob = out + (size_t)bg * 16 * HWPX;

    // ---- stage tiny weights (overlaps cold read) ----
    w1s[tid] = __ldg(w1 + tid);
    for (int i2 = tid; i2 < 768; i2 += 256) w3s[i2] = __ldg(w3 + i2 * 3 + 1);  // kw=1 column
    if (tid < 16) { b1s[tid] = __ldg(b1 + tid); b3s[tid] = __ldg(b3 + tid); gbsh[tid] = __ldg(gnb + tid); }

    // ================= P1: row means (own half) + col partial sums =================
    {
        float* colp_sm = s1;                 // scratch [16][128]
        #pragma unroll 1
        for (int cc = 0; cc < 2; cc++) {
            const int c = wid * 2 + cc;
            const float* g = xb + c * HWPX;
            float4 cs = make_float4(0.f, 0.f, 0.f, 0.f);
            #pragma unroll 1
            for (int i0 = r0; i0 < r0 + 64; i0 += 8) {
                float4 v[8]; float r[8];
                #pragma unroll
                for (int k = 0; k < 8; k++) v[k] = ((const float4*)(g + (i0 + k) * 128))[lane];
                #pragma unroll
                for (int k = 0; k < 8; k++) {
                    cs.x += v[k].x; cs.y += v[k].y; cs.z += v[k].z; cs.w += v[k].w;
                    r[k] = (v[k].x + v[k].y) + (v[k].z + v[k].w);
                }
                #pragma unroll
                for (int off = 16; off; off >>= 1) {
                    #pragma unroll
                    for (int k = 0; k < 8; k++) r[k] += __shfl_down_sync(0xffffffffu, r[k], off);
                }
                if (lane == 0) {
                    #pragma unroll
                    for (int k = 0; k < 8; k++) {
                        const float m = r[k] * (1.f / 128.f);
                        hwb[c * 258 + 1 + i0 + k] = m;
                        __stcg(&g_rowm[bg][hf][c * 64 + (i0 + k - r0)], m);
                    }
                }
            }
            colp_sm[c * 128 + 4 * lane + 0] = cs.x;
            colp_sm[c * 128 + 4 * lane + 1] = cs.y;
            colp_sm[c * 128 + 4 * lane + 2] = cs.z;
            colp_sm[c * 128 + 4 * lane + 3] = cs.w;
            __stcg(&g_colp[bg][hf][c * 128 + 4 * lane + 0], cs.x);
            __stcg(&g_colp[bg][hf][c * 128 + 4 * lane + 1], cs.y);
            __stcg(&g_colp[bg][hf][c * 128 + 4 * lane + 2], cs.z);
            __stcg(&g_colp[bg][hf][c * 128 + 4 * lane + 3], cs.w);
        }
    }
    __threadfence();
    __syncthreads();
    if (tid == 0) {
        atomicExch(&g_flag1[bg][hf], 1);                         // publish
        while (atomicAdd(&g_flag1[bg][ph], 0) == 0) { }          // wait for peer
        __threadfence();
        atomicExch(&g_flag1[bg][ph], 0);                         // consume-reset (restores launch invariant)
    }
    __syncthreads();

    // merge peer row means + build col means
    for (int idx = tid; idx < 1024; idx += 256) {
        const int c = idx >> 6, rr = idx & 63;
        hwb[c * 258 + 1 + pr0 + rr] = __ldcg(&g_rowm[bg][ph][idx]);
    }
    for (int idx = tid; idx < 2048; idx += 256) {
        hwb[(idx >> 7) * 258 + 129 + (idx & 127)] =
            (s1[idx] + __ldcg(&g_colp[bg][ph][idx])) * (1.f / 128.f);
    }
    if (tid < 16) { hwb[tid * 258] = 0.f; hwb[tid * 258 + 257] = 0.f; }
    __syncthreads();

    // ================= kA: channel mix, only the 192 l-values this half needs =================
    for (int idx = tid; idx < 16 * 192; idx += 256) {
        const int o = idx / 192, t = idx - o * 192;
        const int l = (t < 64) ? (r0 + t) : (64 + t);   // own i-rows + full j-side
        float a1 = b1s[o], a2 = b3s[o];
        #pragma unroll
        for (int i = 0; i < 16; i++) {
            const float* h = hwb + i * 258 + l;
            const float h0 = h[0], h1 = h[1], h2 = h[2];
            a1 = fmaf(w1s[o * 16 + i], h1, a1);
            const int wb = (o * 16 + i) * 3;
            a2 = fmaf(w3s[wb], h0, fmaf(w3s[wb + 1], h1, fmaf(w3s[wb + 2], h2, a2)));
        }
        s1[o * 256 + l] = siluf(a1);
        s2[o * 256 + l] = siluf(a2);
    }
    __syncthreads();

    // ================= P2: sums of y, y^2 over own half (descending rows) =================
    #pragma unroll 1
    for (int cc = 0; cc < 2; cc++) {
        const int c = wid * 2 + cc;
        const float* g = xb + c * HWPX;
        const float4 wa = *(const float4*)(s1 + c * 256 + 128 + 4 * lane);
        const float4 wb = *(const float4*)(s2 + c * 256 + 128 + 4 * lane);
        float sa = 0.f, qa = 0.f, sb = 0.f, qb = 0.f;
        #pragma unroll 1
        for (int i0 = r0 + 56; i0 >= r0; i0 -= 8) {
            float4 v[8];
            #pragma unroll
            for (int k = 0; k < 8; k++) v[k] = ((const float4*)(g + (i0 + k) * 128))[lane];
            #pragma unroll
            for (int k = 0; k < 8; k++) {
                const float h1 = s1[c * 256 + i0 + k];
                const float h2 = s2[c * 256 + i0 + k];
                float p;
                p = v[k].x * h1 * wa.x; sa += p; qa = fmaf(p, p, qa);
                p = v[k].y * h1 * wa.y; sa += p; qa = fmaf(p, p, qa);
                p = v[k].z * h1 * wa.z; sa += p; qa = fmaf(p, p, qa);
                p = v[k].w * h1 * wa.w; sa += p; qa = fmaf(p, p, qa);
                p = v[k].x * h2 * wb.x; sb += p; qb = fmaf(p, p, qb);
                p = v[k].y * h2 * wb.y; sb += p; qb = fmaf(p, p, qb);
                p = v[k].z * h2 * wb.z; sb += p; qb = fmaf(p, p, qb);
                p = v[k].w * h2 * wb.w; sb += p; qb = fmaf(p, p, qb);
            }
        }
        #pragma unroll
        for (int off = 16; off; off >>= 1) {
            sa += __shfl_down_sync(0xffffffffu, sa, off);
            qa += __shfl_down_sync(0xffffffffu, qa, off);
            sb += __shfl_down_sync(0xffffffffu, sb, off);
            qb += __shfl_down_sync(0xffffffffu, qb, off);
        }
        if (lane == 0) {
            statp[c * 4 + 0] = sa; statp[c * 4 + 1] = qa;
            statp[c * 4 + 2] = sb; statp[c * 4 + 3] = qb;
        }
    }
    __syncthreads();
    if (tid < 64) __stcg(&g_stat[bg][hf][tid], statp[tid]);
    __threadfence();
    __syncthreads();
    if (tid == 0) {
        atomicExch(&g_flag2[bg][hf], 1);
        while (atomicAdd(&g_flag2[bg][ph], 0) == 0) { }
        __threadfence();
        atomicExch(&g_flag2[bg][ph], 0);
    }
    __syncthreads();

    // ================= kB: softmax(gn_b) identity + norm scalars =================
    if (tid < 16) {
        float m = -1e30f;
        #pragma unroll
        for (int i = 0; i < 16; i++) m = fmaxf(m, gbsh[i]);
        float se = 0.f;
        #pragma unroll
        for (int i = 0; i < 16; i++) se += __expf(gbsh[i] - m);
        const float a = __expf(gbsh[tid] - m) / se;        // a1 == a2 == softmax(gn_b)
        const float S1 = statp[tid * 4 + 0] + __ldcg(&g_stat[bg][ph][tid * 4 + 0]);
        const float Q1 = statp[tid * 4 + 1] + __ldcg(&g_stat[bg][ph][tid * 4 + 1]);
        const float S2 = statp[tid * 4 + 2] + __ldcg(&g_stat[bg][ph][tid * 4 + 2]);
        const float Q2 = statp[tid * 4 + 3] + __ldcg(&g_stat[bg][ph][tid * 4 + 3]);
        const float mu1 = S1 * (1.f / 16384.f);
        const float r1  = rsqrtf(Q1 * (1.f / 16384.f) - mu1 * mu1 + EPSF);
        const float mu2 = S2 * (1.f / 16384.f);
        const float r2  = rsqrtf(Q2 * (1.f / 16384.f) - mu2 * mu2 + EPSF);
        const float gw = __ldg(gnw + tid);
        k1s[tid] = a * gw * r1;
        k2s[tid] = a * gw * r2;
        cpart[tid] = a * (2.f * gbsh[tid] - gw * (mu1 * r1 + mu2 * r2));
    }
    __syncthreads();
    if (tid == 0) {
        float s = 0.f;
        #pragma unroll
        for (int i = 0; i < 16; i++) s += cpart[i];
        Csm = s;
    }
    for (int idx = tid; idx < 1024; idx += 256) {      // fold k into own-row i-side tables
        const int c = idx >> 6, i = r0 + (idx & 63);
        s1[c * 256 + i] *= k1s[c];
        s2[c * 256 + i] *= k2s[c];
    }
    __syncthreads();

    // ================= C: wts + gate + output (own 64 rows, full 16-channel register stash) =================
    {
        const float Cc = Csm;
        #pragma unroll 1
        for (int s = 0; s < 8; s++) {
            const int i = r0 + s * 8 + wid;
            float4 v[16];
            float4 w4 = make_float4(Cc, Cc, Cc, Cc);
            #pragma unroll
            for (int c = 0; c < 16; c++) {
                v[c] = __ldcs((const float4*)(xb + c * HWPX + i * 128) + lane);
                const float a1 = s1[c * 256 + i];
                const float a2 = s2[c * 256 + i];
                const float4 j1 = *(const float4*)(s1 + c * 256 + 128 + 4 * lane);
                const float4 j2 = *(const float4*)(s2 + c * 256 + 128 + 4 * lane);
                w4.x += v[c].x * fmaf(a1, j1.x, a2 * j2.x);
                w4.y += v[c].y * fmaf(a1, j1.y, a2 * j2.y);
                w4.z += v[c].z * fmaf(a1, j1.z, a2 * j2.z);
                w4.w += v[c].w * fmaf(a1, j1.w, a2 * j2.w);
            }
            float4 sw;
            sw.x = siluf(w4.x); sw.y = siluf(w4.y); sw.z = siluf(w4.z); sw.w = siluf(w4.w);
            #pragma unroll
            for (int c = 0; c < 16; c++) {
                float4 o4;
                o4.x = v[c].x * sw.x; o4.y = v[c].y * sw.y;
                o4.z = v[c].z * sw.z; o4.w = v[c].w * sw.w;
                __stcs((float4*)(ob + c * HWPX + i * 128) + lane, o4);
            }
        }
    }
}

// ---------------- launch ----------------
extern "C" void kernel_launch(void* const* d_in, const int* in_sizes, int n_in,
                              void* d_out, int out_size) {
    const float* x    = (const float*)d_in[0];
    const float* w1   = (const float*)d_in[1];
    const float* b1   = (const float*)d_in[2];
    const float* w3   = (const float*)d_in[3];
    const float* b3   = (const float*)d_in[4];
    const float* gn_w = (const float*)d_in[5];
    const float* gn_b = (const float*)d_in[6];
    float* out = (float*)d_out;

    const int smem_bytes = (4096 + 4096 + 16 * 258) * (int)sizeof(float);  // 49280 B
    static bool attr_done = false;
    if (!attr_done) {
        cudaFuncSetAttribute(mega, cudaFuncAttributeMaxDynamicSharedMemorySize, smem_bytes);
        attr_done = true;
    }
    mega<<<256, 256, smem_bytes>>>(x, w1, b1, w3, b3, gn_w, gn_b, out);
}

// round 5
// speedup vs baseline: 1.1479x; 1.1472x over previous
#include <cuda_runtime.h>
#include <math.h>

#define HWPX 16384        // 128*128
#define EPSF 1e-5f

__device__ __forceinline__ float siluf(float v) { return v / (1.0f + __expf(-v)); }

// One block per bg-group (128 blocks, 512 threads). R2 structure; P2 uses the
// separable-moment restructure to cut FMA-pipe pressure 32->24 instr/float4:
//   S = sum_i h_i * (sum_j v*w),  Q = sum_i h_i^2 * (sum_j v^2*w^2)
__global__ __launch_bounds__(512, 1)
void mega(const float* __restrict__ x,
          const float* __restrict__ w1, const float* __restrict__ b1,
          const float* __restrict__ w3, const float* __restrict__ b3,
          const float* __restrict__ gnw, const float* __restrict__ gnb,
          float* __restrict__ out)
{
    extern __shared__ float sm[];
    float* s1  = sm;               // [16][256]  silu(hw1): [c][i<128]=h-side, [c][128+j]=w-side
    float* s2  = sm + 4096;        // [16][256]
    float* hwb = sm + 8192;        // [16][258]  means+halo; aliased as h^2 tables after kA
    float* sq1 = sm + 8192;        // [16][128]  s1^2 (i-side), alias of hwb
    float* sq2 = sm + 8192 + 2048; // [16][128]  s2^2 (i-side)

    __shared__ float w1s[256], w3s[768], b1s[16], b3s[16];
    __shared__ float statv[64], k1s[16], k2s[16], cpart[16], gbsh[16];
    __shared__ float Csm;

    const int bg   = blockIdx.x;
    const int tid  = threadIdx.x;
    const int lane = tid & 31;
    const int wid  = tid >> 5;                   // 0..15 : one warp per image/channel
    const float* xb = x   + (size_t)bg * 16 * HWPX;
    float*       ob = out + (size_t)bg * 16 * HWPX;

    // ---- stage tiny weights (independent of P1, overlaps the cold read) ----
    if (tid < 256) w1s[tid] = __ldg(w1 + tid);
    for (int i2 = tid; i2 < 768; i2 += 512) w3s[i2] = __ldg(w3 + i2 * 3 + 1); // kw=1 column
    if (tid < 16) { b1s[tid] = __ldg(b1 + tid); b3s[tid] = __ldg(b3 + tid); gbsh[tid] = __ldg(gnb + tid); }

    // ================= P1: row means + col means (ascending rows) =================
    {
        const int c = wid;
        const float* g = xb + c * HWPX;
        float* hwc = hwb + c * 258;
        float4 cs = make_float4(0.f, 0.f, 0.f, 0.f);
        #pragma unroll 1
        for (int i0 = 0; i0 < 128; i0 += 8) {
            float4 v[8]; float r[8];
            #pragma unroll
            for (int k = 0; k < 8; k++) v[k] = __ldg((const float4*)(g + (i0 + k) * 128) + lane);
            #pragma unroll
            for (int k = 0; k < 8; k++) {
                cs.x += v[k].x; cs.y += v[k].y; cs.z += v[k].z; cs.w += v[k].w;
                r[k] = (v[k].x + v[k].y) + (v[k].z + v[k].w);
            }
            #pragma unroll
            for (int off = 16; off; off >>= 1) {
                #pragma unroll
                for (int k = 0; k < 8; k++) r[k] += __shfl_down_sync(0xffffffffu, r[k], off);
            }
            if (lane == 0) {
                #pragma unroll
                for (int k = 0; k < 8; k++) hwc[1 + i0 + k] = r[k] * (1.f / 128.f);
            }
        }
        // col means: this warp owns all rows, so cs is the complete column sum
        hwc[129 + 4 * lane + 0] = cs.x * (1.f / 128.f);
        hwc[129 + 4 * lane + 1] = cs.y * (1.f / 128.f);
        hwc[129 + 4 * lane + 2] = cs.z * (1.f / 128.f);
        hwc[129 + 4 * lane + 3] = cs.w * (1.f / 128.f);
        if (lane == 0) { hwc[0] = 0.f; hwc[257] = 0.f; }   // conv halo (zero padding)
    }
    __syncthreads();

    // ================= kA: channel mix over concat length 256 =================
    for (int idx = tid; idx < 4096; idx += 512) {
        const int o = idx >> 8, l = idx & 255;
        float a1 = b1s[o], a2 = b3s[o];
        #pragma unroll
        for (int i = 0; i < 16; i++) {
            const float* h = hwb + i * 258 + l;
            const float h0 = h[0], h1 = h[1], h2 = h[2];
            a1 = fmaf(w1s[o * 16 + i], h1, a1);
            const int wb = (o * 16 + i) * 3;
            a2 = fmaf(w3s[wb], h0, fmaf(w3s[wb + 1], h1, fmaf(w3s[wb + 2], h2, a2)));
        }
        s1[o * 256 + l] = siluf(a1);
        s2[o * 256 + l] = siluf(a2);
    }
    __syncthreads();

    // ---- h^2 tables for the separable Q sums (into dead hwb region) ----
    for (int idx = tid; idx < 2048; idx += 512) {
        const int c = idx >> 7, i = idx & 127;
        const float a = s1[c * 256 + i];
        const float b = s2[c * 256 + i];
        sq1[idx] = a * a;
        sq2[idx] = b * b;
    }
    __syncthreads();

    // ================= P2: separable moment sums (descending rows) =================
    {
        const int c = wid;
        const float* g = xb + c * HWPX;
        const float4 wa = *(const float4*)(s1 + c * 256 + 128 + 4 * lane);
        const float4 wb = *(const float4*)(s2 + c * 256 + 128 + 4 * lane);
        float4 wa2, wb2;
        wa2.x = wa.x * wa.x; wa2.y = wa.y * wa.y; wa2.z = wa.z * wa.z; wa2.w = wa.w * wa.w;
        wb2.x = wb.x * wb.x; wb2.y = wb.y * wb.y; wb2.z = wb.z * wb.z; wb2.w = wb.w * wb.w;
        float sa = 0.f, qa = 0.f, sb = 0.f, qb = 0.f;
        #pragma unroll 1
        for (int i0 = 120; i0 >= 0; i0 -= 8) {
            float4 v[8];
            #pragma unroll
            for (int k = 0; k < 8; k++) v[k] = __ldg((const float4*)(g + (i0 + k) * 128) + lane);
            #pragma unroll
            for (int k = 0; k < 8; k++) {
                const int i = i0 + k;
                const float h1  = s1[c * 256 + i];
                const float h2  = s2[c * 256 + i];
                const float h1q = sq1[c * 128 + i];
                const float h2q = sq2[c * 128 + i];
                // v^2 shared across branches
                const float v2x = v[k].x * v[k].x, v2y = v[k].y * v[k].y;
                const float v2z = v[k].z * v[k].z, v2w = v[k].w * v[k].w;
                // branch 1 dots
                float d1 = v[k].x * wa.x;
                d1 = fmaf(v[k].y, wa.y, d1); d1 = fmaf(v[k].z, wa.z, d1); d1 = fmaf(v[k].w, wa.w, d1);
                float e1 = v2x * wa2.x;
                e1 = fmaf(v2y, wa2.y, e1); e1 = fmaf(v2z, wa2.z, e1); e1 = fmaf(v2w, wa2.w, e1);
                sa = fmaf(h1, d1, sa);
                qa = fmaf(h1q, e1, qa);
                // branch 2 dots
                float d2 = v[k].x * wb.x;
                d2 = fmaf(v[k].y, wb.y, d2); d2 = fmaf(v[k].z, wb.z, d2); d2 = fmaf(v[k].w, wb.w, d2);
                float e2 = v2x * wb2.x;
                e2 = fmaf(v2y, wb2.y, e2); e2 = fmaf(v2z, wb2.z, e2); e2 = fmaf(v2w, wb2.w, e2);
                sb = fmaf(h2, d2, sb);
                qb = fmaf(h2q, e2, qb);
            }
        }
        #pragma unroll
        for (int off = 16; off; off >>= 1) {
            sa += __shfl_down_sync(0xffffffffu, sa, off);
            qa += __shfl_down_sync(0xffffffffu, qa, off);
            sb += __shfl_down_sync(0xffffffffu, sb, off);
            qb += __shfl_down_sync(0xffffffffu, qb, off);
        }
        if (lane == 0) { statv[c * 4] = sa; statv[c * 4 + 1] = qa; statv[c * 4 + 2] = sb; statv[c * 4 + 3] = qb; }
    }
    __syncthreads();

    // ================= kB: scalars =================
    if (tid < 16) {
        float m = -1e30f;
        #pragma unroll
        for (int i = 0; i < 16; i++) m = fmaxf(m, gbsh[i]);
        float se = 0.f;
        #pragma unroll
        for (int i = 0; i < 16; i++) se += __expf(gbsh[i] - m);
        const float a = __expf(gbsh[tid] - m) / se;        // a1 == a2 == softmax(gn_b)
        const float S1 = statv[tid * 4], Q1 = statv[tid * 4 + 1];
        const float S2 = statv[tid * 4 + 2], Q2 = statv[tid * 4 + 3];
        const float mu1 = S1 * (1.f / 16384.f);
        const float r1  = rsqrtf(Q1 * (1.f / 16384.f) - mu1 * mu1 + EPSF);
        const float mu2 = S2 * (1.f / 16384.f);
        const float r2  = rsqrtf(Q2 * (1.f / 16384.f) - mu2 * mu2 + EPSF);
        const float gw = __ldg(gnw + tid);
        k1s[tid] = a * gw * r1;
        k2s[tid] = a * gw * r2;
        cpart[tid] = a * (2.f * gbsh[tid] - gw * (mu1 * r1 + mu2 * r2));
    }
    __syncthreads();
    if (tid == 0) {
        float s = 0.f;
        #pragma unroll
        for (int i = 0; i < 16; i++) s += cpart[i];
        Csm = s;
    }
    // fold k1/k2 into the i-side silu tables (j-side stays unscaled)
    for (int idx = tid; idx < 2048; idx += 512) {
        const int c = idx >> 7, i = idx & 127;
        s1[c * 256 + i] *= k1s[c];
        s2[c * 256 + i] *= k2s[c];
    }
    __syncthreads();

    // ================= C: wts + gate + output (ascending rows, x read once) =================
    {
        const int rloc = tid >> 5;              // 0..15 rows per sub-iteration
        const float Cc = Csm;
        #pragma unroll 1
        for (int s = 0; s < 8; s++) {
            const int i = s * 16 + rloc;
            float4 v[16];
            float4 w4 = make_float4(Cc, Cc, Cc, Cc);
            #pragma unroll
            for (int c = 0; c < 16; c++) {
                v[c] = __ldcs((const float4*)(xb + c * HWPX + i * 128) + lane);
                const float a1 = s1[c * 256 + i];
                const float a2 = s2[c * 256 + i];
                const float4 j1 = *(const float4*)(s1 + c * 256 + 128 + 4 * lane);
                const float4 j2 = *(const float4*)(s2 + c * 256 + 128 + 4 * lane);
                w4.x += v[c].x * fmaf(a1, j1.x, a2 * j2.x);
                w4.y += v[c].y * fmaf(a1, j1.y, a2 * j2.y);
                w4.z += v[c].z * fmaf(a1, j1.z, a2 * j2.z);
                w4.w += v[c].w * fmaf(a1, j1.w, a2 * j2.w);
            }
            float4 sw;
            sw.x = siluf(w4.x); sw.y = siluf(w4.y); sw.z = siluf(w4.z); sw.w = siluf(w4.w);
            #pragma unroll
            for (int c = 0; c < 16; c++) {
                float4 o4;
                o4.x = v[c].x * sw.x; o4.y = v[c].y * sw.y;
                o4.z = v[c].z * sw.z; o4.w = v[c].w * sw.w;
                __stcs((float4*)(ob + c * HWPX + i * 128) + lane, o4);
            }
        }
    }
}

// ---------------- launch ----------------
extern "C" void kernel_launch(void* const* d_in, const int* in_sizes, int n_in,
                              void* d_out, int out_size) {
    const float* x    = (const float*)d_in[0];
    const float* w1   = (const float*)d_in[1];
    const float* b1   = (const float*)d_in[2];
    const float* w3   = (const float*)d_in[3];
    const float* b3   = (const float*)d_in[4];
    const float* gn_w = (const float*)d_in[5];
    const float* gn_b = (const float*)d_in[6];
    float* out = (float*)d_out;

    const int smem_bytes = (4096 + 4096 + 16 * 258) * (int)sizeof(float);  // 49280 B
    static bool attr_done = false;
    if (!attr_done) {
        cudaFuncSetAttribute(mega, cudaFuncAttributeMaxDynamicSharedMemorySize, smem_bytes);
        attr_done = true;
    }
    mega<<<128, 512, smem_bytes>>>(x, w1, b1, w3, b3, gn_w, gn_b, out);
}

// round 6
// speedup vs baseline: 1.1871x; 1.0342x over previous
#include <cuda_runtime.h>
#include <math.h>

#define HWPX 16384        // 128*128
#define EPSF 1e-5f

__device__ __forceinline__ float siluf(float v) { return v / (1.0f + __expf(-v)); }

// One block per bg-group (128 blocks, 512 threads). R5 structure; P1 and P2 are
// software-pipelined (ping-pong register double-buffering) so each warp keeps
// 8 float4 loads in flight while computing on the previous batch.
__global__ __launch_bounds__(512, 1)
void mega(const float* __restrict__ x,
          const float* __restrict__ w1, const float* __restrict__ b1,
          const float* __restrict__ w3, const float* __restrict__ b3,
          const float* __restrict__ gnw, const float* __restrict__ gnb,
          float* __restrict__ out)
{
    extern __shared__ float sm[];
    float* s1  = sm;               // [16][256]  silu(hw1): [c][i<128]=h-side, [c][128+j]=w-side
    float* s2  = sm + 4096;        // [16][256]
    float* hwb = sm + 8192;        // [16][258]  means+halo; aliased as h^2 tables after kA
    float* sq1 = sm + 8192;        // [16][128]  s1^2 (i-side), alias of hwb
    float* sq2 = sm + 8192 + 2048; // [16][128]  s2^2 (i-side)

    __shared__ float w1s[256], w3s[768], b1s[16], b3s[16];
    __shared__ float statv[64], k1s[16], k2s[16], cpart[16], gbsh[16];
    __shared__ float Csm;

    const int bg   = blockIdx.x;
    const int tid  = threadIdx.x;
    const int lane = tid & 31;
    const int wid  = tid >> 5;                   // 0..15 : one warp per image/channel
    const float* xb = x   + (size_t)bg * 16 * HWPX;
    float*       ob = out + (size_t)bg * 16 * HWPX;

    // ---- stage tiny weights (independent of P1, overlaps the cold read) ----
    if (tid < 256) w1s[tid] = __ldg(w1 + tid);
    for (int i2 = tid; i2 < 768; i2 += 512) w3s[i2] = __ldg(w3 + i2 * 3 + 1); // kw=1 column
    if (tid < 16) { b1s[tid] = __ldg(b1 + tid); b3s[tid] = __ldg(b3 + tid); gbsh[tid] = __ldg(gnb + tid); }

    // ================= P1: row means + col means (pipelined, ascending) =================
    {
        const int c = wid;
        const float* g = xb + c * HWPX;
        float* hwc = hwb + c * 258;
        float4 cs = make_float4(0.f, 0.f, 0.f, 0.f);
        float4 va[8], vb[8];

        #pragma unroll
        for (int k = 0; k < 8; k++) va[k] = __ldg((const float4*)(g + k * 128) + lane);

        #pragma unroll 1
        for (int i0 = 0; i0 < 128; i0 += 16) {
            // prefetch batch B while computing batch A
            #pragma unroll
            for (int k = 0; k < 8; k++) vb[k] = __ldg((const float4*)(g + (i0 + 8 + k) * 128) + lane);
            {
                float r[8];
                #pragma unroll
                for (int k = 0; k < 8; k++) {
                    cs.x += va[k].x; cs.y += va[k].y; cs.z += va[k].z; cs.w += va[k].w;
                    r[k] = (va[k].x + va[k].y) + (va[k].z + va[k].w);
                }
                #pragma unroll
                for (int off = 16; off; off >>= 1) {
                    #pragma unroll
                    for (int k = 0; k < 8; k++) r[k] += __shfl_down_sync(0xffffffffu, r[k], off);
                }
                if (lane == 0) {
                    #pragma unroll
                    for (int k = 0; k < 8; k++) hwc[1 + i0 + k] = r[k] * (1.f / 128.f);
                }
            }
            // prefetch next A while computing B
            if (i0 + 16 < 128) {
                #pragma unroll
                for (int k = 0; k < 8; k++) va[k] = __ldg((const float4*)(g + (i0 + 16 + k) * 128) + lane);
            }
            {
                float r[8];
                #pragma unroll
                for (int k = 0; k < 8; k++) {
                    cs.x += vb[k].x; cs.y += vb[k].y; cs.z += vb[k].z; cs.w += vb[k].w;
                    r[k] = (vb[k].x + vb[k].y) + (vb[k].z + vb[k].w);
                }
                #pragma unroll
                for (int off = 16; off; off >>= 1) {
                    #pragma unroll
                    for (int k = 0; k < 8; k++) r[k] += __shfl_down_sync(0xffffffffu, r[k], off);
                }
                if (lane == 0) {
                    #pragma unroll
                    for (int k = 0; k < 8; k++) hwc[1 + i0 + 8 + k] = r[k] * (1.f / 128.f);
                }
            }
        }
        hwc[129 + 4 * lane + 0] = cs.x * (1.f / 128.f);
        hwc[129 + 4 * lane + 1] = cs.y * (1.f / 128.f);
        hwc[129 + 4 * lane + 2] = cs.z * (1.f / 128.f);
        hwc[129 + 4 * lane + 3] = cs.w * (1.f / 128.f);
        if (lane == 0) { hwc[0] = 0.f; hwc[257] = 0.f; }   // conv halo (zero padding)
    }
    __syncthreads();

    // ================= kA: channel mix over concat length 256 =================
    for (int idx = tid; idx < 4096; idx += 512) {
        const int o = idx >> 8, l = idx & 255;
        float a1 = b1s[o], a2 = b3s[o];
        #pragma unroll
        for (int i = 0; i < 16; i++) {
            const float* h = hwb + i * 258 + l;
            const float h0 = h[0], h1 = h[1], h2 = h[2];
            a1 = fmaf(w1s[o * 16 + i], h1, a1);
            const int wb = (o * 16 + i) * 3;
            a2 = fmaf(w3s[wb], h0, fmaf(w3s[wb + 1], h1, fmaf(w3s[wb + 2], h2, a2)));
        }
        s1[o * 256 + l] = siluf(a1);
        s2[o * 256 + l] = siluf(a2);
    }
    __syncthreads();

    // ---- h^2 tables for the separable Q sums (into dead hwb region) ----
    for (int idx = tid; idx < 2048; idx += 512) {
        const int c = idx >> 7, i = idx & 127;
        const float a = s1[c * 256 + i];
        const float b = s2[c * 256 + i];
        sq1[idx] = a * a;
        sq2[idx] = b * b;
    }
    __syncthreads();

    // ================= P2: separable moment sums (pipelined, descending) =================
    {
        const int c = wid;
        const float* g = xb + c * HWPX;
        const float4 wa = *(const float4*)(s1 + c * 256 + 128 + 4 * lane);
        const float4 wb = *(const float4*)(s2 + c * 256 + 128 + 4 * lane);
        float4 wa2, wb2;
        wa2.x = wa.x * wa.x; wa2.y = wa.y * wa.y; wa2.z = wa.z * wa.z; wa2.w = wa.w * wa.w;
        wb2.x = wb.x * wb.x; wb2.y = wb.y * wb.y; wb2.z = wb.z * wb.z; wb2.w = wb.w * wb.w;
        float sa = 0.f, qa = 0.f, sb = 0.f, qb = 0.f;
        float4 va[8], vb[8];

        #pragma unroll
        for (int k = 0; k < 8; k++) va[k] = __ldg((const float4*)(g + (120 + k) * 128) + lane);

        #define P2_BODY(BUF, IBASE)                                                         \
        {                                                                                   \
            _Pragma("unroll")                                                               \
            for (int k = 0; k < 8; k++) {                                                   \
                const int i = (IBASE) + k;                                                  \
                const float h1  = s1[c * 256 + i];                                          \
                const float h2  = s2[c * 256 + i];                                          \
                const float h1q = sq1[c * 128 + i];                                         \
                const float h2q = sq2[c * 128 + i];                                         \
                const float v2x = BUF[k].x * BUF[k].x, v2y = BUF[k].y * BUF[k].y;           \
                const float v2z = BUF[k].z * BUF[k].z, v2w = BUF[k].w * BUF[k].w;           \
                float d1 = BUF[k].x * wa.x;                                                 \
                d1 = fmaf(BUF[k].y, wa.y, d1); d1 = fmaf(BUF[k].z, wa.z, d1);               \
                d1 = fmaf(BUF[k].w, wa.w, d1);                                              \
                float e1 = v2x * wa2.x;                                                     \
                e1 = fmaf(v2y, wa2.y, e1); e1 = fmaf(v2z, wa2.z, e1);                       \
                e1 = fmaf(v2w, wa2.w, e1);                                                  \
                sa = fmaf(h1, d1, sa);                                                      \
                qa = fmaf(h1q, e1, qa);                                                     \
                float d2 = BUF[k].x * wb.x;                                                 \
                d2 = fmaf(BUF[k].y, wb.y, d2); d2 = fmaf(BUF[k].z, wb.z, d2);               \
                d2 = fmaf(BUF[k].w, wb.w, d2);                                              \
                float e2 = v2x * wb2.x;                                                     \
                e2 = fmaf(v2y, wb2.y, e2); e2 = fmaf(v2z, wb2.z, e2);                       \
                e2 = fmaf(v2w, wb2.w, e2);                                                  \
                sb = fmaf(h2, d2, sb);                                                      \
                qb = fmaf(h2q, e2, qb);                                                     \
            }                                                                               \
        }

        #pragma unroll 1
        for (int i0 = 120; i0 >= 0; i0 -= 16) {
            #pragma unroll
            for (int k = 0; k < 8; k++) vb[k] = __ldg((const float4*)(g + (i0 - 8 + k) * 128) + lane);
            P2_BODY(va, i0)
            if (i0 - 16 >= 0) {
                #pragma unroll
                for (int k = 0; k < 8; k++) va[k] = __ldg((const float4*)(g + (i0 - 16 + k) * 128) + lane);
            }
            P2_BODY(vb, i0 - 8)
        }
        #undef P2_BODY

        #pragma unroll
        for (int off = 16; off; off >>= 1) {
            sa += __shfl_down_sync(0xffffffffu, sa, off);
            qa += __shfl_down_sync(0xffffffffu, qa, off);
            sb += __shfl_down_sync(0xffffffffu, sb, off);
            qb += __shfl_down_sync(0xffffffffu, qb, off);
        }
        if (lane == 0) { statv[c * 4] = sa; statv[c * 4 + 1] = qa; statv[c * 4 + 2] = sb; statv[c * 4 + 3] = qb; }
    }
    __syncthreads();

    // ================= kB: scalars =================
    if (tid < 16) {
        float m = -1e30f;
        #pragma unroll
        for (int i = 0; i < 16; i++) m = fmaxf(m, gbsh[i]);
        float se = 0.f;
        #pragma unroll
        for (int i = 0; i < 16; i++) se += __expf(gbsh[i] - m);
        const float a = __expf(gbsh[tid] - m) / se;        // a1 == a2 == softmax(gn_b)
        const float S1 = statv[tid * 4], Q1 = statv[tid * 4 + 1];
        const float S2 = statv[tid * 4 + 2], Q2 = statv[tid * 4 + 3];
        const float mu1 = S1 * (1.f / 16384.f);
        const float r1  = rsqrtf(Q1 * (1.f / 16384.f) - mu1 * mu1 + EPSF);
        const float mu2 = S2 * (1.f / 16384.f);
        const float r2  = rsqrtf(Q2 * (1.f / 16384.f) - mu2 * mu2 + EPSF);
        const float gw = __ldg(gnw + tid);
        k1s[tid] = a * gw * r1;
        k2s[tid] = a * gw * r2;
        cpart[tid] = a * (2.f * gbsh[tid] - gw * (mu1 * r1 + mu2 * r2));
    }
    __syncthreads();
    if (tid == 0) {
        float s = 0.f;
        #pragma unroll
        for (int i = 0; i < 16; i++) s += cpart[i];
        Csm = s;
    }
    // fold k1/k2 into the i-side silu tables (j-side stays unscaled)
    for (int idx = tid; idx < 2048; idx += 512) {
        const int c = idx >> 7, i = idx & 127;
        s1[c * 256 + i] *= k1s[c];
        s2[c * 256 + i] *= k2s[c];
    }
    __syncthreads();

    // ================= C: wts + gate + output (ascending rows, x read once) =================
    {
        const int rloc = tid >> 5;              // 0..15 rows per sub-iteration
        const float Cc = Csm;
        #pragma unroll 1
        for (int s = 0; s < 8; s++) {
            const int i = s * 16 + rloc;
            float4 v[16];
            float4 w4 = make_float4(Cc, Cc, Cc, Cc);
            #pragma unroll
            for (int c = 0; c < 16; c++) {
                v[c] = __ldcs((const float4*)(xb + c * HWPX + i * 128) + lane);
                const float a1 = s1[c * 256 + i];
                const float a2 = s2[c * 256 + i];
                const float4 j1 = *(const float4*)(s1 + c * 256 + 128 + 4 * lane);
                const float4 j2 = *(const float4*)(s2 + c * 256 + 128 + 4 * lane);
                w4.x += v[c].x * fmaf(a1, j1.x, a2 * j2.x);
                w4.y += v[c].y * fmaf(a1, j1.y, a2 * j2.y);
                w4.z += v[c].z * fmaf(a1, j1.z, a2 * j2.z);
                w4.w += v[c].w * fmaf(a1, j1.w, a2 * j2.w);
            }
            float4 sw;
            sw.x = siluf(w4.x); sw.y = siluf(w4.y); sw.z = siluf(w4.z); sw.w = siluf(w4.w);
            #pragma unroll
            for (int c = 0; c < 16; c++) {
                float4 o4;
                o4.x = v[c].x * sw.x; o4.y = v[c].y * sw.y;
                o4.z = v[c].z * sw.z; o4.w = v[c].w * sw.w;
                __stcs((float4*)(ob + c * HWPX + i * 128) + lane, o4);
            }
        }
    }
}

// ---------------- launch ----------------
extern "C" void kernel_launch(void* const* d_in, const int* in_sizes, int n_in,
                              void* d_out, int out_size) {
    const float* x    = (const float*)d_in[0];
    const float* w1   = (const float*)d_in[1];
    const float* b1   = (const float*)d_in[2];
    const float* w3   = (const float*)d_in[3];
    const float* b3   = (const float*)d_in[4];
    const float* gn_w = (const float*)d_in[5];
    const float* gn_b = (const float*)d_in[6];
    float* out = (float*)d_out;

    const int smem_bytes = (4096 + 4096 + 16 * 258) * (int)sizeof(float);  // 49280 B
    static bool attr_done = false;
    if (!attr_done) {
        cudaFuncSetAttribute(mega, cudaFuncAttributeMaxDynamicSharedMemorySize, smem_bytes);
        attr_done = true;
    }
    mega<<<128, 512, smem_bytes>>>(x, w1, b1, w3, b3, gn_w, gn_b, out);
}